// round 6
// baseline (speedup 1.0000x reference)
#include <cuda_runtime.h>
#include <cuda_bf16.h>
#include <math.h>

// ---------------------------------------------------------------------------
// LSTM: B=32, T=1024, D=512, H=512
// out = [outputs (B*T*H), final_states (B*H)] fp32
//
// Phase 1: Z = X @ Wx + b            (gemm_xwx, 32768x2048x512 fp32, f32x2)
// Phase 2: persistent recurrence     (lstm_recur_main, 128 blocks = 4 grp x 32)
// Phase 3: gather final states       (final_copy, dtype-sniffing lengths)
// ---------------------------------------------------------------------------

#define BATCH 32
#define SEQ   1024
#define DIM   512
#define HID   512
#define GATE4 2048   // 4*HID

#define NGROUP 4
#define BPG    32             // blocks per group
#define GBATCH (BATCH/NGROUP) // 8 batches per group
#define CHUNK  (HID/BPG)      // 16 hidden cols per block -> 64 gate cols

// ---- scratch (device globals: allocation-free) ----
__device__ float g_Z[(size_t)BATCH * SEQ * GATE4];     // 256 MB
__device__ float g_h[2][HID][BATCH];                   // ping-pong h, [k][b]
__device__ volatile unsigned g_cnt[NGROUP];
__device__ volatile unsigned g_gen[NGROUP];

// ---- packed f32x2 helpers (FFMA2 is only reachable via PTX) ----
__device__ __forceinline__ void ffma2(unsigned long long& d,
                                      unsigned long long a,
                                      unsigned long long b) {
    asm volatile("fma.rn.f32x2 %0, %1, %2, %0;" : "+l"(d) : "l"(a), "l"(b));
}
__device__ __forceinline__ unsigned long long dup2(float x) {
    unsigned long long r;
    unsigned xi = __float_as_uint(x);
    asm("mov.b64 %0, {%1, %1};" : "=l"(r) : "r"(xi));
    return r;
}

// ---------------------------------------------------------------------------
// Phase 1: Z[r][c] = sum_k X[r][k]*Wx[k][c] + b[c]
// BM=128 BN=64 BK=16, 256 threads, thread tile 8x4 (f32x2 packed over cols)
// ---------------------------------------------------------------------------
#define BM 128
#define BN 64
#define BK 16

__global__ __launch_bounds__(256) void gemm_xwx(const float* __restrict__ X,
                                                const float* __restrict__ Wx,
                                                const float* __restrict__ bias) {
    __shared__ float As[BK][BM + 4];   // transposed, padded vs bank conflicts
    __shared__ float Bs[BK][BN];

    const int rowBase = blockIdx.x * BM;
    const int colBase = blockIdx.y * BN;
    const int tid = threadIdx.x;
    const int tx = tid & 15;          // 16 col-quads
    const int ty = tid >> 4;          // 16 row-octets

    unsigned long long acc2[8][2];    // [row][col-pair], 4 cols per row
#pragma unroll
    for (int i = 0; i < 8; i++) { acc2[i][0] = 0ull; acc2[i][1] = 0ull; }

    for (int k0 = 0; k0 < DIM; k0 += BK) {
        // A tile: 128x16 -> As[k][m]; 512 float4 loads by 256 threads
#pragma unroll
        for (int f = tid; f < 512; f += 256) {
            int m = f >> 2;
            int kk = (f & 3) * 4;
            float4 v = *(const float4*)&X[(size_t)(rowBase + m) * DIM + k0 + kk];
            As[kk + 0][m] = v.x;
            As[kk + 1][m] = v.y;
            As[kk + 2][m] = v.z;
            As[kk + 3][m] = v.w;
        }
        // B tile: 16x64 -> Bs[k][n]; 256 float4 loads
        {
            int kk = tid >> 4;
            int n = (tid & 15) * 4;
            *(float4*)&Bs[kk][n] =
                *(const float4*)&Wx[(size_t)(k0 + kk) * GATE4 + colBase + n];
        }
        __syncthreads();

#pragma unroll
        for (int kk = 0; kk < BK; kk++) {
            float4 a0 = *(float4*)&As[kk][ty * 8];
            float4 a1 = *(float4*)&As[kk][ty * 8 + 4];
            ulonglong2 bp = *(ulonglong2*)&Bs[kk][tx * 4];
            unsigned long long ad[8] = {dup2(a0.x), dup2(a0.y), dup2(a0.z), dup2(a0.w),
                                        dup2(a1.x), dup2(a1.y), dup2(a1.z), dup2(a1.w)};
#pragma unroll
            for (int i = 0; i < 8; i++) {
                ffma2(acc2[i][0], ad[i], bp.x);
                ffma2(acc2[i][1], ad[i], bp.y);
            }
        }
        __syncthreads();
    }

    // epilogue: + bias, store
    const int col = colBase + tx * 4;
    float4 bb = *(const float4*)&bias[col];
#pragma unroll
    for (int ri = 0; ri < 8; ri++) {
        int row = rowBase + ty * 8 + ri;
        float2 p0 = *(float2*)&acc2[ri][0];
        float2 p1 = *(float2*)&acc2[ri][1];
        float4 o;
        o.x = p0.x + bb.x;
        o.y = p0.y + bb.y;
        o.z = p1.x + bb.z;
        o.w = p1.y + bb.w;
        *(float4*)&g_Z[(size_t)row * GATE4 + col] = o;
    }
}

// ---------------------------------------------------------------------------
// Group barrier: 32 resident blocks, sense via monotonic generation counter.
// Replay-safe (cnt returns to 0, gen keeps growing; equality test tolerates wrap)
// ---------------------------------------------------------------------------
__device__ __forceinline__ void group_barrier(int grp) {
    __syncthreads();
    if (threadIdx.x == 0) {
        __threadfence();
        unsigned seen = g_gen[grp];
        unsigned my = atomicAdd((unsigned*)&g_cnt[grp], 1u);
        if (my == BPG - 1) {
            atomicExch((unsigned*)&g_cnt[grp], 0u);
            __threadfence();
            g_gen[grp] = seen + 1;
        } else {
            while (g_gen[grp] == seen) { __nanosleep(32); }
        }
        __threadfence();
    }
    __syncthreads();
}

// ---------------------------------------------------------------------------
// Phase 2: persistent recurrence.
// 128 blocks = 4 groups x 32. Block owns (8 batches, 16 hidden cols).
// Wh slice (512 x 64 gate cols = 128 KB) stays in SMEM for all 1024 steps.
// c state lives in registers of threads 0..127.
// ---------------------------------------------------------------------------
#define SMEM_FLOATS (DIM * 64 + DIM * GBATCH + 8 * 520)
#define SMEM_BYTES  (SMEM_FLOATS * 4)

__global__ __launch_bounds__(256, 1) void lstm_recur_main(
    const float* __restrict__ Wh, float* __restrict__ out) {
    const int tid = threadIdx.x;
    const int blk = blockIdx.x;
    const int grp = blk >> 5;
    const int bg  = blk & 31;
    const int B0  = grp * GBATCH;
    const int chunk0 = bg * CHUNK;

    extern __shared__ float smem[];
    float* w_s = smem;                       // [512][64] gate-col slice of Wh
    float* h_s = smem + DIM * 64;            // [512][8]  h for our 8 batches
    float* z_s = h_s + DIM * GBATCH;         // [8][520]  split-k partials

    // --- one-time: load Wh slice into SMEM ---
    // local col c = gate*16 + j  ->  global col = gate*512 + chunk0 + j
    for (int i = tid; i < DIM * 64; i += 256) {
        int k = i >> 6, c = i & 63;
        int col = ((c >> 4) << 9) + chunk0 + (c & 15);
        w_s[i] = Wh[(size_t)k * GATE4 + col];
    }

    // --- one-time: zero our slice of h buffer 0 (fresh on every replay) ---
    const int b_my = tid >> 4;   // 0..7   (threads 0..127)
    const int j_my = tid & 15;   // 0..15
    if (tid < 128) {
        g_h[0][chunk0 + j_my][B0 + b_my] = 0.f;
    }
    float c_state = 0.f;

    group_barrier(grp);

    const int w = tid >> 5;      // warp id -> k slice [w*64, w*64+64)
    const int l = tid & 31;
    const int cq = l >> 1;       // 0..15 col-quad
    const int bq = l & 1;        // 0..1  batch-half

    for (int t = 0; t < SEQ; t++) {
        // prefetch input-projection gate values (DRAM latency hidden by GEMM)
        float zi = 0.f, zf = 0.f, zg = 0.f, zo = 0.f;
        if (tid < 128) {
            const float* zr = g_Z +
                ((size_t)(B0 + b_my) * SEQ + t) * GATE4 + chunk0 + j_my;
            zi = zr[0];
            zf = zr[512];
            zg = zr[1024];
            zo = zr[1536];
        }

        // load h for our 8 batches: h_s[k][b] <- g_h[t&1][k][B0+b]
        const float* hbuf = &g_h[t & 1][0][0];
        for (int i = tid; i < DIM * GBATCH; i += 256) {
            int k = i >> 3, b = i & 7;
            h_s[i] = hbuf[k * BATCH + B0 + b];
        }
        __syncthreads();

        // split-k GEMM: warp covers 64 k, thread tile 4 batches x 4 cols (f32x2)
        unsigned long long acc2[4][2];
#pragma unroll
        for (int i = 0; i < 4; i++) { acc2[i][0] = 0ull; acc2[i][1] = 0ull; }

        const int k0 = w * 64;
#pragma unroll 4
        for (int k = k0; k < k0 + 64; k++) {
            float4 h4 = *(float4*)&h_s[k * GBATCH + bq * 4];
            ulonglong2 wv = *(ulonglong2*)&w_s[k * 64 + cq * 4];
            unsigned long long hd[4] = {dup2(h4.x), dup2(h4.y),
                                        dup2(h4.z), dup2(h4.w)};
#pragma unroll
            for (int i = 0; i < 4; i++) {
                ffma2(acc2[i][0], hd[i], wv.x);
                ffma2(acc2[i][1], hd[i], wv.y);
            }
        }

        // write partials (8-byte aligned float2 stores)
#pragma unroll
        for (int i = 0; i < 4; i++) {
#pragma unroll
            for (int j2 = 0; j2 < 2; j2++) {
                float2 v = *(float2*)&acc2[i][j2];
                *(float2*)&z_s[w * 520 + (bq * 4 + i) * 64 + cq * 4 + j2 * 2] = v;
            }
        }
        __syncthreads();

        if (tid < 128) {
            float si = zi, sf = zf, sg = zg, so = zo;
#pragma unroll
            for (int w2 = 0; w2 < 8; w2++) {
                const float* p = &z_s[w2 * 520 + b_my * 64 + j_my];
                si += p[0];
                sf += p[16];
                sg += p[32];
                so += p[48];
            }
            float ig = 1.f / (1.f + __expf(-si));
            float fg = 1.f / (1.f + __expf(-sf));
            float gg = tanhf(sg);
            float og = 1.f / (1.f + __expf(-so));
            c_state = fg * c_state + ig * gg;
            float h_new = og * tanhf(c_state);

            g_h[(t + 1) & 1][chunk0 + j_my][B0 + b_my] = h_new;
            out[((size_t)(B0 + b_my) * SEQ + t) * HID + chunk0 + j_my] = h_new;
        }

        group_barrier(grp);
    }
}

// ---------------------------------------------------------------------------
// Phase 3: final_states[b] = outputs[b, max(0, len-1), :]
// lengths dtype unknown (reference says int64; harness contract lists only
// int32). Two-level detection:
//   (a) host: in_sizes[1] == 2*BATCH  => raw int64 (passed as n_len)
//   (b) device word-sniff over first 128 bytes: int64 data (< 1024) has all
//       odd 32-bit words zero; int32 random lengths ~never do.
// t is clamped to [0, SEQ-1] so a wrong guess can never fault.
// ---------------------------------------------------------------------------
__global__ void final_copy(const float* __restrict__ out,
                           const void* __restrict__ lenraw,
                           int n_len,
                           float* __restrict__ fin) {
    const int b = blockIdx.x;
    const int* s32 = (const int*)lenraw;

    __shared__ int is64_s;
    if (threadIdx.x == 0) {
        int is64;
        if (n_len >= 2 * BATCH) {
            is64 = 1;                      // harness reported 8-byte elements
        } else {
            int orv = 0;
#pragma unroll
            for (int i = 1; i < 32; i += 2) orv |= s32[i];
            is64 = (orv == 0) ? 1 : 0;     // sniff: odd words all zero => int64
        }
        is64_s = is64;
    }
    __syncthreads();

    long long len;
    if (is64_s) len = ((const long long*)lenraw)[b];
    else        len = (long long)s32[b];

    long long t = len > 0 ? len - 1 : 0;
    if (t < 0) t = 0;
    if (t > SEQ - 1) t = SEQ - 1;

    fin[b * HID + threadIdx.x] =
        out[((size_t)b * SEQ + (size_t)t) * HID + threadIdx.x];
}

// ---------------------------------------------------------------------------
extern "C" void kernel_launch(void* const* d_in, const int* in_sizes, int n_in,
                              void* d_out, int out_size) {
    const float* X       = (const float*)d_in[0];
    const void*  lengths = (const void*)d_in[1];
    const float* Wx      = (const float*)d_in[2];
    const float* Wh      = (const float*)d_in[3];
    const float* bias    = (const float*)d_in[4];
    float* out = (float*)d_out;

    (void)n_in; (void)out_size;

    cudaFuncSetAttribute(lstm_recur_main,
                         cudaFuncAttributeMaxDynamicSharedMemorySize,
                         SMEM_BYTES);

    dim3 g1(BATCH * SEQ / BM, GATE4 / BN);
    gemm_xwx<<<g1, 256>>>(X, Wx, bias);

    lstm_recur_main<<<NGROUP * BPG, 256, SMEM_BYTES>>>(Wh, out);

    final_copy<<<BATCH, HID>>>(out, lengths, in_sizes[1],
                               out + (size_t)BATCH * SEQ * HID);
}

// round 8
// speedup vs baseline: 1.0025x; 1.0025x over previous
#include <cuda_runtime.h>
#include <cuda_bf16.h>
#include <math.h>

// ---------------------------------------------------------------------------
// LSTM: B=32, T=1024, D=512, H=512
// out = [outputs (B*T*H), final_states (B*H)] fp32
// ---------------------------------------------------------------------------

#define BATCH 32
#define SEQ   1024
#define DIM   512
#define HID   512
#define GATE4 2048   // 4*HID

#define NGROUP 4
#define BPG    32             // blocks per group
#define GBATCH (BATCH/NGROUP) // 8 batches per group
#define CHUNK  (HID/BPG)      // 16 hidden cols per block -> 64 gate cols

// ---- scratch (device globals: allocation-free) ----
__device__ float g_Z[(size_t)BATCH * SEQ * GATE4];     // 256 MB
__device__ float g_h[2][HID][BATCH];                   // ping-pong h, [k][b]

// Barrier state: each counter in its OWN 128B line (4 groups x atomics +
// ~31 spinners each previously hammered ONE L2 line -> LTS serialization).
struct __align__(128) PadCtr { unsigned v; unsigned pad[31]; };
__device__ PadCtr g_cnt2[NGROUP];
__device__ PadCtr g_gen2[NGROUP];

// ---- packed f32x2 helpers (FFMA2 is only reachable via PTX) ----
__device__ __forceinline__ void ffma2(unsigned long long& d,
                                      unsigned long long a,
                                      unsigned long long b) {
    asm volatile("fma.rn.f32x2 %0, %1, %2, %0;" : "+l"(d) : "l"(a), "l"(b));
}
__device__ __forceinline__ unsigned long long dup2(float x) {
    unsigned long long r;
    unsigned xi = __float_as_uint(x);
    asm("mov.b64 %0, {%1, %1};" : "=l"(r) : "r"(xi));
    return r;
}

// ---------------------------------------------------------------------------
// Phase 1: Z[r][c] = sum_k X[r][k]*Wx[k][c] + b[c]
// BM=128 BN=64 BK=16, 256 threads, thread tile 8 rows x 4 cols.
// Accumulators packed over ROW PAIRS: A row-pairs load naturally as u64 from
// As[kk][m] (zero MOVs); only 4 B scalars are dup2'd per kk (was 8 A dups).
// ---------------------------------------------------------------------------
#define BM 128
#define BN 64
#define BK 16

__global__ __launch_bounds__(256) void gemm_xwx(const float* __restrict__ X,
                                                const float* __restrict__ Wx,
                                                const float* __restrict__ bias) {
    __shared__ float As[BK][BM + 4];   // transposed, padded
    __shared__ float Bs[BK][BN];

    const int rowBase = blockIdx.x * BM;
    const int colBase = blockIdx.y * BN;
    const int tid = threadIdx.x;
    const int tx = tid & 15;          // 16 col-quads
    const int ty = tid >> 4;          // 16 row-octets

    // acc2[p][j]: row-pair p (rows 2p,2p+1 of this thread's 8), col j
    unsigned long long acc2[4][4];
#pragma unroll
    for (int p = 0; p < 4; p++)
#pragma unroll
        for (int j = 0; j < 4; j++) acc2[p][j] = 0ull;

    for (int k0 = 0; k0 < DIM; k0 += BK) {
        // A tile: 128x16 -> As[k][m]
#pragma unroll
        for (int f = tid; f < 512; f += 256) {
            int m = f >> 2;
            int kk = (f & 3) * 4;
            float4 v = *(const float4*)&X[(size_t)(rowBase + m) * DIM + k0 + kk];
            As[kk + 0][m] = v.x;
            As[kk + 1][m] = v.y;
            As[kk + 2][m] = v.z;
            As[kk + 3][m] = v.w;
        }
        // B tile: 16x64 -> Bs[k][n]
        {
            int kk = tid >> 4;
            int n = (tid & 15) * 4;
            *(float4*)&Bs[kk][n] =
                *(const float4*)&Wx[(size_t)(k0 + kk) * GATE4 + colBase + n];
        }
        __syncthreads();

#pragma unroll
        for (int kk = 0; kk < BK; kk++) {
            // natural row pairs: (2p, 2p+1) packed in u64
            ulonglong2 a01 = *(ulonglong2*)&As[kk][ty * 8];      // pairs 0,1
            ulonglong2 a23 = *(ulonglong2*)&As[kk][ty * 8 + 4];  // pairs 2,3
            float4 b4 = *(float4*)&Bs[kk][tx * 4];
            unsigned long long bd[4] = {dup2(b4.x), dup2(b4.y),
                                        dup2(b4.z), dup2(b4.w)};
            unsigned long long ap[4] = {a01.x, a01.y, a23.x, a23.y};
#pragma unroll
            for (int p = 0; p < 4; p++)
#pragma unroll
                for (int j = 0; j < 4; j++)
                    ffma2(acc2[p][j], ap[p], bd[j]);
        }
        __syncthreads();
    }

    // epilogue: + bias, store (two rows per pair)
    const int col = colBase + tx * 4;
    float4 bb = *(const float4*)&bias[col];
#pragma unroll
    for (int p = 0; p < 4; p++) {
        float4 oe, oo;
        float2 f0 = *(float2*)&acc2[p][0];
        float2 f1 = *(float2*)&acc2[p][1];
        float2 f2 = *(float2*)&acc2[p][2];
        float2 f3 = *(float2*)&acc2[p][3];
        oe.x = f0.x + bb.x; oo.x = f0.y + bb.x;
        oe.y = f1.x + bb.y; oo.y = f1.y + bb.y;
        oe.z = f2.x + bb.z; oo.z = f2.y + bb.z;
        oe.w = f3.x + bb.w; oo.w = f3.y + bb.w;
        int row = rowBase + ty * 8 + 2 * p;
        *(float4*)&g_Z[(size_t)row * GATE4 + col] = oe;
        *(float4*)&g_Z[(size_t)(row + 1) * GATE4 + col] = oo;
    }
}

// ---------------------------------------------------------------------------
// Group barrier (padded lines, light backoff). Replay-safe monotonic gen.
// ---------------------------------------------------------------------------
__device__ __forceinline__ void group_barrier(int grp) {
    __syncthreads();
    if (threadIdx.x == 0) {
        __threadfence();
        volatile unsigned* genp = &g_gen2[grp].v;
        unsigned seen = *genp;
        unsigned my = atomicAdd(&g_cnt2[grp].v, 1u);
        if (my == BPG - 1) {
            g_cnt2[grp].v = 0u;          // only leader writes; safe
            __threadfence();
            *genp = seen + 1;
        } else {
            while (*genp == seen) { __nanosleep(16); }
        }
        __threadfence();
    }
    __syncthreads();
}

// ---------------------------------------------------------------------------
// Phase 2: persistent recurrence.
// 128 blocks = 4 groups x 32. Block owns (8 batches, 16 hidden cols).
// SMEM: Wh slice 128KB + h duplicated-pairs 32KB + partials 16.6KB.
// Inner loop: 1 LDS.128 (w col-pairs) + 4 LDS.64 (dup'd h, broadcast) +
// 8 FFMA2 — zero MOVs.
// ---------------------------------------------------------------------------
#define W_FLOATS   (DIM * 64)
#define H2_U64S    (DIM * GBATCH)
#define Z_FLOATS   (8 * 520)
#define SMEM_BYTES (W_FLOATS * 4 + H2_U64S * 8 + Z_FLOATS * 4)

__global__ __launch_bounds__(256, 1) void lstm_recur_main(
    const float* __restrict__ Wh, float* __restrict__ out) {
    const int tid = threadIdx.x;
    const int blk = blockIdx.x;
    const int grp = blk >> 5;
    const int bg  = blk & 31;
    const int B0  = grp * GBATCH;
    const int chunk0 = bg * CHUNK;

    extern __shared__ char smem_raw[];
    float* w_s = (float*)smem_raw;                              // [512][64]
    unsigned long long* h2_s =
        (unsigned long long*)(smem_raw + W_FLOATS * 4);         // [512][8] (h,h)
    float* z_s = (float*)(smem_raw + W_FLOATS * 4 + H2_U64S * 8); // [8][520]

    // one-time: load Wh slice. local col c=gate*16+j -> global gate*512+chunk0+j
    for (int i = tid; i < W_FLOATS; i += 256) {
        int k = i >> 6, c = i & 63;
        int col = ((c >> 4) << 9) + chunk0 + (c & 15);
        w_s[i] = Wh[(size_t)k * GATE4 + col];
    }

    const int b_my = tid >> 4;   // 0..7  (threads 0..127)
    const int j_my = tid & 15;   // 0..15
    if (tid < 128) {
        g_h[0][chunk0 + j_my][B0 + b_my] = 0.f;
    }
    float c_state = 0.f;

    // prefetch z(0) before the fence barrier (g_Z ready: prior kernel)
    float zi = 0.f, zf = 0.f, zg = 0.f, zo = 0.f;
    if (tid < 128) {
        const float* zr = g_Z + ((size_t)(B0 + b_my) * SEQ + 0) * GATE4 +
                          chunk0 + j_my;
        zi = zr[0]; zf = zr[512]; zg = zr[1024]; zo = zr[1536];
    }

    group_barrier(grp);

    const int w = tid >> 5;      // warp id -> k slice [w*64, w*64+64)
    const int l = tid & 31;
    const int cq = l >> 1;       // 0..15 col-quad
    const int bq = l & 1;        // 0..1  batch-half

    for (int t = 0; t < SEQ; t++) {
        // fill duplicated h pairs: h2_s[k*8+b] = (h,h)
        const float* hbuf = &g_h[t & 1][0][0];
        for (int i = tid; i < H2_U64S; i += 256) {
            int k = i >> 3, b = i & 7;
            float v = hbuf[k * BATCH + B0 + b];
            h2_s[i] = dup2(v);
        }
        __syncthreads();

        // split-k GEMM: warp covers 64 k, thread tile 4 batches x 4 cols
        unsigned long long acc2[4][2];
#pragma unroll
        for (int i = 0; i < 4; i++) { acc2[i][0] = 0ull; acc2[i][1] = 0ull; }

        const int k0 = w * 64;
#pragma unroll 4
        for (int k = k0; k < k0 + 64; k++) {
            ulonglong2 wv = *(ulonglong2*)&w_s[k * 64 + cq * 4];
            const unsigned long long* hp = &h2_s[k * GBATCH + bq * 4];
#pragma unroll
            for (int i = 0; i < 4; i++) {
                unsigned long long hd = hp[i];
                ffma2(acc2[i][0], hd, wv.x);
                ffma2(acc2[i][1], hd, wv.y);
            }
        }

        // write partials
#pragma unroll
        for (int i = 0; i < 4; i++) {
#pragma unroll
            for (int j2 = 0; j2 < 2; j2++) {
                float2 v = *(float2*)&acc2[i][j2];
                *(float2*)&z_s[w * 520 + (bq * 4 + i) * 64 + cq * 4 + j2 * 2] = v;
            }
        }
        __syncthreads();

        if (tid < 128) {
            float si = zi, sf = zf, sg = zg, so = zo;
#pragma unroll
            for (int w2 = 0; w2 < 8; w2++) {
                const float* p = &z_s[w2 * 520 + b_my * 64 + j_my];
                si += p[0];
                sf += p[16];
                sg += p[32];
                so += p[48];
            }
            float ig = 1.f / (1.f + __expf(-si));
            float fg = 1.f / (1.f + __expf(-sf));
            float gg = tanhf(sg);
            float og = 1.f / (1.f + __expf(-so));
            c_state = fg * c_state + ig * gg;
            float h_new = og * tanhf(c_state);

            g_h[(t + 1) & 1][chunk0 + j_my][B0 + b_my] = h_new;
            out[((size_t)(B0 + b_my) * SEQ + t) * HID + chunk0 + j_my] = h_new;

            // prefetch z(t+1) BEFORE barrier: DRAM latency hides in the wait
            if (t + 1 < SEQ) {
                const float* zr = g_Z +
                    ((size_t)(B0 + b_my) * SEQ + (t + 1)) * GATE4 +
                    chunk0 + j_my;
                zi = zr[0]; zf = zr[512]; zg = zr[1024]; zo = zr[1536];
            }
        }

        group_barrier(grp);
    }
}

// ---------------------------------------------------------------------------
// Phase 3: final_states[b] = outputs[b, max(0, len-1), :]
// dtype-sniffing (int64 vs int32 lengths), clamped indexing.
// ---------------------------------------------------------------------------
__global__ void final_copy(const float* __restrict__ out,
                           const void* __restrict__ lenraw,
                           int n_len,
                           float* __restrict__ fin) {
    const int b = blockIdx.x;
    const int* s32 = (const int*)lenraw;

    __shared__ int is64_s;
    if (threadIdx.x == 0) {
        int is64;
        if (n_len >= 2 * BATCH) {
            is64 = 1;
        } else {
            int orv = 0;
#pragma unroll
            for (int i = 1; i < 32; i += 2) orv |= s32[i];
            is64 = (orv == 0) ? 1 : 0;
        }
        is64_s = is64;
    }
    __syncthreads();

    long long len;
    if (is64_s) len = ((const long long*)lenraw)[b];
    else        len = (long long)s32[b];

    long long t = len > 0 ? len - 1 : 0;
    if (t < 0) t = 0;
    if (t > SEQ - 1) t = SEQ - 1;

    fin[b * HID + threadIdx.x] =
        out[((size_t)b * SEQ + (size_t)t) * HID + threadIdx.x];
}

// ---------------------------------------------------------------------------
extern "C" void kernel_launch(void* const* d_in, const int* in_sizes, int n_in,
                              void* d_out, int out_size) {
    const float* X       = (const float*)d_in[0];
    const void*  lengths = (const void*)d_in[1];
    const float* Wx      = (const float*)d_in[2];
    const float* Wh      = (const float*)d_in[3];
    const float* bias    = (const float*)d_in[4];
    float* out = (float*)d_out;

    (void)n_in; (void)out_size;

    cudaFuncSetAttribute(lstm_recur_main,
                         cudaFuncAttributeMaxDynamicSharedMemorySize,
                         SMEM_BYTES);

    dim3 g1(BATCH * SEQ / BM, GATE4 / BN);
    gemm_xwx<<<g1, 256>>>(X, Wx, bias);

    lstm_recur_main<<<NGROUP * BPG, 256, SMEM_BYTES>>>(Wh, out);

    final_copy<<<BATCH, HID>>>(out, lengths, in_sizes[1],
                               out + (size_t)BATCH * SEQ * HID);
}

// round 9
// speedup vs baseline: 1.1224x; 1.1196x over previous
#include <cuda_runtime.h>
#include <cuda_bf16.h>
#include <math.h>

// ---------------------------------------------------------------------------
// LSTM: B=32, T=1024, D=512, H=512
// out = [outputs (B*T*H), final_states (B*H)] fp32
// ---------------------------------------------------------------------------

#define BATCH 32
#define SEQ   1024
#define DIM   512
#define HID   512
#define GATE4 2048   // 4*HID

#define NGROUP 4
#define BPG    32             // blocks per group
#define GBATCH (BATCH/NGROUP) // 8 batches per group
#define CHUNK  (HID/BPG)      // 16 hidden cols per block -> 64 gate cols

// ---- scratch (device globals: allocation-free) ----
__device__ float g_Z[(size_t)BATCH * SEQ * GATE4];     // 256 MB
__device__ float g_h[2][HID][BATCH];                   // ping-pong h, [k][b]

// Distributed publish flags: one padded 128B line per block, monotonic value.
// flag == base + v  means "this block has published h(v-1)" (v=1 => h(0)).
// Every replay adds exactly SEQ+1 increments per flag -> all flags equal at
// every kernel launch; each block reads its OWN flag as base.
struct __align__(128) PadCtr { unsigned v; unsigned pad[31]; };
__device__ PadCtr g_flag[NGROUP * BPG];

// ---- acquire/release + packed f32x2 helpers ----
__device__ __forceinline__ unsigned ld_acq(const unsigned* p) {
    unsigned v;
    asm volatile("ld.acquire.gpu.global.u32 %0, [%1];" : "=r"(v) : "l"(p) : "memory");
    return v;
}
__device__ __forceinline__ void st_rel(unsigned* p, unsigned v) {
    asm volatile("st.release.gpu.global.u32 [%0], %1;" :: "l"(p), "r"(v) : "memory");
}
__device__ __forceinline__ void ffma2(unsigned long long& d,
                                      unsigned long long a,
                                      unsigned long long b) {
    asm volatile("fma.rn.f32x2 %0, %1, %2, %0;" : "+l"(d) : "l"(a), "l"(b));
}
__device__ __forceinline__ unsigned long long dup2(float x) {
    unsigned long long r;
    unsigned xi = __float_as_uint(x);
    asm("mov.b64 %0, {%1, %1};" : "=l"(r) : "r"(xi));
    return r;
}

// ---------------------------------------------------------------------------
// Phase 1: Z[r][c] = sum_k X[r][k]*Wx[k][c] + b[c]
// BM=128 BN=64 BK=16, 256 threads, row-pair packed f32x2 accumulators.
// (proven R8: 1.44 ms, ~70% of f32x2 issue ceiling)
// ---------------------------------------------------------------------------
#define BM 128
#define BN 64
#define BK 16

__global__ __launch_bounds__(256) void gemm_xwx(const float* __restrict__ X,
                                                const float* __restrict__ Wx,
                                                const float* __restrict__ bias) {
    __shared__ float As[BK][BM + 4];
    __shared__ float Bs[BK][BN];

    const int rowBase = blockIdx.x * BM;
    const int colBase = blockIdx.y * BN;
    const int tid = threadIdx.x;
    const int tx = tid & 15;
    const int ty = tid >> 4;

    unsigned long long acc2[4][4];
#pragma unroll
    for (int p = 0; p < 4; p++)
#pragma unroll
        for (int j = 0; j < 4; j++) acc2[p][j] = 0ull;

    for (int k0 = 0; k0 < DIM; k0 += BK) {
#pragma unroll
        for (int f = tid; f < 512; f += 256) {
            int m = f >> 2;
            int kk = (f & 3) * 4;
            float4 v = *(const float4*)&X[(size_t)(rowBase + m) * DIM + k0 + kk];
            As[kk + 0][m] = v.x;
            As[kk + 1][m] = v.y;
            As[kk + 2][m] = v.z;
            As[kk + 3][m] = v.w;
        }
        {
            int kk = tid >> 4;
            int n = (tid & 15) * 4;
            *(float4*)&Bs[kk][n] =
                *(const float4*)&Wx[(size_t)(k0 + kk) * GATE4 + colBase + n];
        }
        __syncthreads();

#pragma unroll
        for (int kk = 0; kk < BK; kk++) {
            ulonglong2 a01 = *(ulonglong2*)&As[kk][ty * 8];
            ulonglong2 a23 = *(ulonglong2*)&As[kk][ty * 8 + 4];
            float4 b4 = *(float4*)&Bs[kk][tx * 4];
            unsigned long long bd[4] = {dup2(b4.x), dup2(b4.y),
                                        dup2(b4.z), dup2(b4.w)};
            unsigned long long ap[4] = {a01.x, a01.y, a23.x, a23.y};
#pragma unroll
            for (int p = 0; p < 4; p++)
#pragma unroll
                for (int j = 0; j < 4; j++)
                    ffma2(acc2[p][j], ap[p], bd[j]);
        }
        __syncthreads();
    }

    const int col = colBase + tx * 4;
    float4 bb = *(const float4*)&bias[col];
#pragma unroll
    for (int p = 0; p < 4; p++) {
        float4 oe, oo;
        float2 f0 = *(float2*)&acc2[p][0];
        float2 f1 = *(float2*)&acc2[p][1];
        float2 f2 = *(float2*)&acc2[p][2];
        float2 f3 = *(float2*)&acc2[p][3];
        oe.x = f0.x + bb.x; oo.x = f0.y + bb.x;
        oe.y = f1.x + bb.y; oo.y = f1.y + bb.y;
        oe.z = f2.x + bb.z; oo.z = f2.y + bb.z;
        oe.w = f3.x + bb.w; oo.w = f3.y + bb.w;
        int row = rowBase + ty * 8 + 2 * p;
        *(float4*)&g_Z[(size_t)row * GATE4 + col] = oe;
        *(float4*)&g_Z[(size_t)(row + 1) * GATE4 + col] = oo;
    }
}

// ---------------------------------------------------------------------------
// Phase 2: persistent recurrence, dataflow-synced.
// 128 blocks = 4 groups x 32. Block owns (8 batches, 16 hidden cols).
// Per step: wait 32 publish flags (warp-parallel acquire poll) -> h-fill ->
// split-k GEMM from SMEM-resident Wh -> gates -> publish h(t+1) via
// fence + bar + one release store. Depth-2 ping-pong h gives backpressure:
// publishing h(t) proves h-fill(t-1) done, so h(t-1)'s buffer is reusable.
// ---------------------------------------------------------------------------
#define W_FLOATS   (DIM * 64)
#define H2_U64S    (DIM * GBATCH)
#define Z_FLOATS   (8 * 520)
#define SMEM_BYTES (W_FLOATS * 4 + H2_U64S * 8 + Z_FLOATS * 4)

__global__ __launch_bounds__(256, 1) void lstm_recur_main(
    const float* __restrict__ Wh, float* __restrict__ out) {
    const int tid = threadIdx.x;
    const int blk = blockIdx.x;
    const int grp = blk >> 5;
    const int bg  = blk & 31;
    const int B0  = grp * GBATCH;
    const int chunk0 = bg * CHUNK;

    extern __shared__ char smem_raw[];
    float* w_s = (float*)smem_raw;                                // [512][64]
    unsigned long long* h2_s =
        (unsigned long long*)(smem_raw + W_FLOATS * 4);           // [512][8]
    float* z_s = (float*)(smem_raw + W_FLOATS * 4 + H2_U64S * 8); // [8][520]

    // base of the monotonic flag space (own flag; uniform across blocks)
    const unsigned fbase = g_flag[blk].v;

    // one-time: load Wh slice. local col c=gate*16+j -> global gate*512+chunk0+j
    for (int i = tid; i < W_FLOATS; i += 256) {
        int k = i >> 6, c = i & 63;
        int col = ((c >> 4) << 9) + chunk0 + (c & 15);
        w_s[i] = Wh[(size_t)k * GATE4 + col];
    }

    const int b_my = tid >> 4;   // 0..7  (threads 0..127)
    const int j_my = tid & 15;   // 0..15
    if (tid < 128) {
        g_h[0][chunk0 + j_my][B0 + b_my] = 0.f;   // publish h(0) = 0
    }
    float c_state = 0.f;

    // prefetch z(0) (g_Z ready: prior kernel in stream order)
    float zi = 0.f, zf = 0.f, zg = 0.f, zo = 0.f;
    if (tid < 128) {
        const float* zr = g_Z + ((size_t)(B0 + b_my) * SEQ) * GATE4 +
                          chunk0 + j_my;
        zi = zr[0]; zf = zr[512]; zg = zr[1024]; zo = zr[1536];
    }

    __threadfence();
    __syncthreads();
    if (tid == 0) st_rel(&g_flag[blk].v, fbase + 1);   // "h(0) published"

    const int w = tid >> 5;      // warp id -> k slice [w*64, w*64+64)
    const int l = tid & 31;
    const int cq = l >> 1;       // 0..15 col-quad
    const int bq = l & 1;        // 0..1  batch-half

    for (int t = 0; t < SEQ; t++) {
        // ---- wait: all 32 group flags >= fbase + 1 + t  (h(t) published) ----
        if (tid < 32) {
            const unsigned tgt = fbase + 1 + (unsigned)t;
            unsigned* fp = &g_flag[grp * BPG + tid].v;
            while (!__all_sync(0xffffffffu,
                               (int)(ld_acq(fp) - tgt) >= 0)) { }
        }
        __syncthreads();

        // ---- h-fill: h2_s[k*8+b] = (h,h) from g_h[t&1] ----
        const float* hbuf = &g_h[t & 1][0][0];
        for (int i = tid; i < H2_U64S; i += 256) {
            int k = i >> 3, b = i & 7;
            float v = hbuf[k * BATCH + B0 + b];
            h2_s[i] = dup2(v);
        }
        __syncthreads();

        // ---- split-k GEMM: warp covers 64 k, thread tile 4b x 4c (f32x2) ----
        unsigned long long acc2[4][2];
#pragma unroll
        for (int i = 0; i < 4; i++) { acc2[i][0] = 0ull; acc2[i][1] = 0ull; }

        const int k0 = w * 64;
#pragma unroll 4
        for (int k = k0; k < k0 + 64; k++) {
            ulonglong2 wv = *(ulonglong2*)&w_s[k * 64 + cq * 4];
            const unsigned long long* hp = &h2_s[k * GBATCH + bq * 4];
#pragma unroll
            for (int i = 0; i < 4; i++) {
                unsigned long long hd = hp[i];
                ffma2(acc2[i][0], hd, wv.x);
                ffma2(acc2[i][1], hd, wv.y);
            }
        }

#pragma unroll
        for (int i = 0; i < 4; i++) {
#pragma unroll
            for (int j2 = 0; j2 < 2; j2++) {
                float2 v = *(float2*)&acc2[i][j2];
                *(float2*)&z_s[w * 520 + (bq * 4 + i) * 64 + cq * 4 + j2 * 2] = v;
            }
        }
        __syncthreads();

        // ---- gates + publish h(t+1) ----
        if (tid < 128) {
            float si = zi, sf = zf, sg = zg, so = zo;
#pragma unroll
            for (int w2 = 0; w2 < 8; w2++) {
                const float* p = &z_s[w2 * 520 + b_my * 64 + j_my];
                si += p[0];
                sf += p[16];
                sg += p[32];
                so += p[48];
            }
            float ig = 1.f / (1.f + __expf(-si));
            float fg = 1.f / (1.f + __expf(-sf));
            float gg = tanhf(sg);
            float og = 1.f / (1.f + __expf(-so));
            c_state = fg * c_state + ig * gg;
            float h_new = og * tanhf(c_state);

            g_h[(t + 1) & 1][chunk0 + j_my][B0 + b_my] = h_new;
            out[((size_t)(B0 + b_my) * SEQ + t) * HID + chunk0 + j_my] = h_new;

            // prefetch z(t+1): DRAM latency hides under next wait
            if (t + 1 < SEQ) {
                const float* zr = g_Z +
                    ((size_t)(B0 + b_my) * SEQ + (t + 1)) * GATE4 +
                    chunk0 + j_my;
                zi = zr[0]; zf = zr[512]; zg = zr[1024]; zo = zr[1536];
            }
            __threadfence();   // order this thread's h store before flag
        }
        __syncthreads();
        if (tid == 0) st_rel(&g_flag[blk].v, fbase + 2 + (unsigned)t);
    }
}

// ---------------------------------------------------------------------------
// Phase 3: final_states[b] = outputs[b, max(0, len-1), :]
// dtype-sniffing (int64 vs int32 lengths), clamped indexing.
// ---------------------------------------------------------------------------
__global__ void final_copy(const float* __restrict__ out,
                           const void* __restrict__ lenraw,
                           int n_len,
                           float* __restrict__ fin) {
    const int b = blockIdx.x;
    const int* s32 = (const int*)lenraw;

    __shared__ int is64_s;
    if (threadIdx.x == 0) {
        int is64;
        if (n_len >= 2 * BATCH) {
            is64 = 1;
        } else {
            int orv = 0;
#pragma unroll
            for (int i = 1; i < 32; i += 2) orv |= s32[i];
            is64 = (orv == 0) ? 1 : 0;
        }
        is64_s = is64;
    }
    __syncthreads();

    long long len;
    if (is64_s) len = ((const long long*)lenraw)[b];
    else        len = (long long)s32[b];

    long long t = len > 0 ? len - 1 : 0;
    if (t < 0) t = 0;
    if (t > SEQ - 1) t = SEQ - 1;

    fin[b * HID + threadIdx.x] =
        out[((size_t)b * SEQ + (size_t)t) * HID + threadIdx.x];
}

// ---------------------------------------------------------------------------
extern "C" void kernel_launch(void* const* d_in, const int* in_sizes, int n_in,
                              void* d_out, int out_size) {
    const float* X       = (const float*)d_in[0];
    const void*  lengths = (const void*)d_in[1];
    const float* Wx      = (const float*)d_in[2];
    const float* Wh      = (const float*)d_in[3];
    const float* bias    = (const float*)d_in[4];
    float* out = (float*)d_out;

    (void)n_in; (void)out_size;

    cudaFuncSetAttribute(lstm_recur_main,
                         cudaFuncAttributeMaxDynamicSharedMemorySize,
                         SMEM_BYTES);

    dim3 g1(BATCH * SEQ / BM, GATE4 / BN);
    gemm_xwx<<<g1, 256>>>(X, Wx, bias);

    lstm_recur_main<<<NGROUP * BPG, 256, SMEM_BYTES>>>(Wh, out);

    final_copy<<<BATCH, HID>>>(out, lengths, in_sizes[1],
                               out + (size_t)BATCH * SEQ * HID);
}